// round 5
// baseline (speedup 1.0000x reference)
#include <cuda_runtime.h>
#include <cuda_bf16.h>
#include <cstdint>

// ===========================================================================
// GCN: out = Anorm @ relu(Anorm @ relu(Anorm @ (x W1) + b1) W2 + b2) W3 + b3
// GEMMs: bf16 mma.sync 3-term split (fp32-accurate).
// SpMM: int16 per-row-quantized gather (half the L2 traffic), PRMT+FADD dequant.
// ===========================================================================

#define NNODES 8192
#define FDIM   512
#define KTOT   1536
#define WORDS_PER_ROW 256
#define MAXDEG 192

__device__ unsigned int g_bits[NNODES * WORDS_PER_ROW];   // 8 MB
__device__ unsigned int g_self[WORDS_PER_ROW];
__device__ float g_dinv[NNODES];
__device__ float g_selfcoef[NNODES];
__device__ int   g_cols[NNODES * MAXDEG];
__device__ int   g_cnt[NNODES];
__device__ int   g_is64;
__device__ float g_buf0[NNODES * FDIM];                   // 16 MB (GEMM out)
__device__ float g_buf1[NNODES * FDIM];                   // 16 MB (layer act)
__device__ __nv_bfloat16 g_abf[NNODES * KTOT];            // 24 MB
__device__ __nv_bfloat16 g_bbf[512 * KTOT];               // 1.5 MB
__device__ unsigned short g_q[NNODES * FDIM];             // 8 MB quantized GEMM out
__device__ float g_qs[NNODES];                            // per-row scale

// ===========================================================================
// Graph build
// ===========================================================================
__global__ void k_clear_bits() {
    int idx = blockIdx.x * blockDim.x + threadIdx.x;
    int row = idx >> 8;
    int w   = idx & 255;
    g_bits[idx] = (w == (row >> 5)) ? (1u << (row & 31)) : 0u;
    if (idx < WORDS_PER_ROW) g_self[idx] = 0u;
    if (idx == 0) g_is64 = 1;
}

__global__ void k_detect(const int* __restrict__ w, int nwords) {
    int i = blockIdx.x * blockDim.x + threadIdx.x;
    int idx = 2 * i + 1;
    if (idx < nwords && w[idx] != 0) g_is64 = 0;
}

__global__ void k_scatter(const int* __restrict__ w, int E) {
    int i = blockIdx.x * blockDim.x + threadIdx.x;
    if (i >= E) return;
    int a, b;
    if (g_is64) { a = w[2 * i]; b = w[2 * E + 2 * i]; }
    else        { a = w[i];     b = w[E + i]; }
    if ((unsigned)a >= NNODES || (unsigned)b >= NNODES) return;
    atomicOr(&g_bits[(size_t)a * WORDS_PER_ROW + (b >> 5)], 1u << (b & 31));
    atomicOr(&g_bits[(size_t)b * WORDS_PER_ROW + (a >> 5)], 1u << (a & 31));
    if (a == b) atomicOr(&g_self[a >> 5], 1u << (a & 31));
}

__global__ void k_build_rows() {
    int warp = (blockIdx.x * blockDim.x + threadIdx.x) >> 5;
    int lane = threadIdx.x & 31;
    if (warp >= NNODES) return;
    int row = warp;

    unsigned int w[8];
    const unsigned int* base = &g_bits[(size_t)row * WORDS_PER_ROW + lane * 8];
#pragma unroll
    for (int t = 0; t < 8; t++) w[t] = base[t];

    int dw = row >> 5;
    if ((dw >> 3) == lane) w[dw & 7] &= ~(1u << (row & 31));

    unsigned int cnt = 0;
#pragma unroll
    for (int t = 0; t < 8; t++) cnt += __popc(w[t]);

    unsigned int incl = cnt;
#pragma unroll
    for (int d = 1; d < 32; d <<= 1) {
        unsigned int v = __shfl_up_sync(0xFFFFFFFFu, incl, d);
        if (lane >= d) incl += v;
    }
    unsigned int excl  = incl - cnt;
    unsigned int total = __shfl_sync(0xFFFFFFFFu, incl, 31);

    int* cols = &g_cols[(size_t)row * MAXDEG];
    unsigned int o = excl;
#pragma unroll
    for (int t = 0; t < 8; t++) {
        unsigned int bits = w[t];
        int colbase = (lane * 8 + t) * 32;
        while (bits) {
            int b = __ffs(bits) - 1;
            bits &= bits - 1;
            if (o < MAXDEG) cols[o] = colbase + b;
            o++;
        }
    }

    if (lane == 0) {
        int self = (g_self[row >> 5] >> (row & 31)) & 1;
        float deg = (float)total + 1.0f + (float)self;
        float di = rsqrtf(deg);
        g_dinv[row] = di;
        g_selfcoef[row] = (1.0f + (float)self) * di;
        g_cnt[row] = (int)(total < MAXDEG ? total : MAXDEG);
    }
}

// ===========================================================================
// Split-precision expansion
// ===========================================================================
__global__ void k_expandA(const float* __restrict__ A, __nv_bfloat16* __restrict__ out) {
    int idx = blockIdx.x * blockDim.x + threadIdx.x;
    int row = idx >> 9;
    int k   = idx & 511;
    float a = A[idx];
    __nv_bfloat16 ah = __float2bfloat16_rn(a);
    __nv_bfloat16 al = __float2bfloat16_rn(a - __bfloat162float(ah));
    size_t b = (size_t)row * KTOT + k;
    out[b] = ah;
    out[b + 512] = ah;
    out[b + 1024] = al;
}

__global__ void k_expandB(const float* __restrict__ W, __nv_bfloat16* __restrict__ out, int Ncol) {
    int idx = blockIdx.x * blockDim.x + threadIdx.x;
    if (idx >= Ncol * 512) return;
    int n = idx >> 9;
    int k = idx & 511;
    float v = W[(size_t)k * Ncol + n];
    __nv_bfloat16 bh = __float2bfloat16_rn(v);
    __nv_bfloat16 bl = __float2bfloat16_rn(v - __bfloat162float(bh));
    size_t b = (size_t)n * KTOT + k;
    out[b] = bh;
    out[b + 512] = bl;
    out[b + 1024] = bh;
}

// ===========================================================================
// bf16 mma.sync GEMM (unchanged from R4 passing version)
// ===========================================================================
#define GPAD 40
#define GNIT (KTOT / 32)

__device__ __forceinline__ void cp16(uint32_t saddr, const void* g) {
    asm volatile("cp.async.cg.shared.global [%0], [%1], 16;" :: "r"(saddr), "l"(g));
}
__device__ __forceinline__ void cp_commit() { asm volatile("cp.async.commit_group;"); }
template <int N> __device__ __forceinline__ void cp_wait() {
    asm volatile("cp.async.wait_group %0;" :: "n"(N));
}

__device__ __forceinline__ void mma16816(float* c, uint32_t a0, uint32_t a1,
                                         uint32_t a2, uint32_t a3,
                                         uint32_t b0, uint32_t b1) {
    asm volatile(
        "mma.sync.aligned.m16n8k16.row.col.f32.bf16.bf16.f32 "
        "{%0,%1,%2,%3}, {%4,%5,%6,%7}, {%8,%9}, {%0,%1,%2,%3};"
        : "+f"(c[0]), "+f"(c[1]), "+f"(c[2]), "+f"(c[3])
        : "r"(a0), "r"(a1), "r"(a2), "r"(a3), "r"(b0), "r"(b1));
}

__global__ __launch_bounds__(256) void k_gemm_mma(const __nv_bfloat16* __restrict__ Aexp,
                                                  const __nv_bfloat16* __restrict__ Bexp,
                                                  float* __restrict__ C, int Ncol) {
    __shared__ __nv_bfloat16 sA[2][128 * GPAD];
    __shared__ __nv_bfloat16 sB[2][128 * GPAD];

    int tid  = threadIdx.x;
    int wid  = tid >> 5;
    int lane = tid & 31;
    int g    = lane >> 2;
    int tig  = lane & 3;

    int m0 = blockIdx.y * 128;
    int n0 = blockIdx.x * 128;
    int wm = (wid >> 2) * 64;
    int wn = (wid & 3) * 32;

    const __nv_bfloat16* Ab = Aexp + (size_t)m0 * KTOT;
    const __nv_bfloat16* Bb = Bexp + (size_t)n0 * KTOT;

    int c0i = tid;
    int r0 = c0i >> 2, s0 = (c0i & 3) * 8;
    int c1i = tid + 256;
    int r1 = c1i >> 2, s1 = (c1i & 3) * 8;

    uint32_t sA0 = (uint32_t)__cvta_generic_to_shared(&sA[0][0]);
    uint32_t sB0 = (uint32_t)__cvta_generic_to_shared(&sB[0][0]);
    const uint32_t bufstride = 128 * GPAD * 2;

    float acc[4][4][4];
#pragma unroll
    for (int mt = 0; mt < 4; mt++)
#pragma unroll
        for (int nt = 0; nt < 4; nt++)
#pragma unroll
            for (int j = 0; j < 4; j++) acc[mt][nt][j] = 0.0f;

    {
        cp16(sA0 + (uint32_t)(r0 * GPAD + s0) * 2, Ab + (size_t)r0 * KTOT + s0);
        cp16(sA0 + (uint32_t)(r1 * GPAD + s1) * 2, Ab + (size_t)r1 * KTOT + s1);
        cp16(sB0 + (uint32_t)(r0 * GPAD + s0) * 2, Bb + (size_t)r0 * KTOT + s0);
        cp16(sB0 + (uint32_t)(r1 * GPAD + s1) * 2, Bb + (size_t)r1 * KTOT + s1);
        cp_commit();
    }

    for (int it = 0; it < GNIT; it++) {
        int b = it & 1;
        if (it + 1 < GNIT) {
            int nb = (it + 1) & 1;
            int k0 = (it + 1) * 32;
            uint32_t sa = sA0 + nb * bufstride;
            uint32_t sbm = sB0 + nb * bufstride;
            cp16(sa  + (uint32_t)(r0 * GPAD + s0) * 2, Ab + (size_t)r0 * KTOT + k0 + s0);
            cp16(sa  + (uint32_t)(r1 * GPAD + s1) * 2, Ab + (size_t)r1 * KTOT + k0 + s1);
            cp16(sbm + (uint32_t)(r0 * GPAD + s0) * 2, Bb + (size_t)r0 * KTOT + k0 + s0);
            cp16(sbm + (uint32_t)(r1 * GPAD + s1) * 2, Bb + (size_t)r1 * KTOT + k0 + s1);
            cp_commit();
            cp_wait<1>();
        } else {
            cp_wait<0>();
        }
        __syncthreads();

        const __nv_bfloat16* At = sA[b];
        const __nv_bfloat16* Bt = sB[b];
#pragma unroll
        for (int ks = 0; ks < 32; ks += 16) {
            int kk = ks + tig * 2;
            uint32_t bf[4][2];
#pragma unroll
            for (int nt = 0; nt < 4; nt++) {
                int n = wn + nt * 8 + g;
                bf[nt][0] = *(const uint32_t*)&Bt[n * GPAD + kk];
                bf[nt][1] = *(const uint32_t*)&Bt[n * GPAD + kk + 8];
            }
#pragma unroll
            for (int mt = 0; mt < 4; mt++) {
                int m = wm + mt * 16 + g;
                uint32_t a0 = *(const uint32_t*)&At[m * GPAD + kk];
                uint32_t a1 = *(const uint32_t*)&At[(m + 8) * GPAD + kk];
                uint32_t a2 = *(const uint32_t*)&At[m * GPAD + kk + 8];
                uint32_t a3 = *(const uint32_t*)&At[(m + 8) * GPAD + kk + 8];
#pragma unroll
                for (int nt = 0; nt < 4; nt++)
                    mma16816(acc[mt][nt], a0, a1, a2, a3, bf[nt][0], bf[nt][1]);
            }
        }
        __syncthreads();
    }

#pragma unroll
    for (int mt = 0; mt < 4; mt++) {
        int row = m0 + wm + mt * 16 + g;
#pragma unroll
        for (int nt = 0; nt < 4; nt++) {
            int col = n0 + wn + nt * 8 + tig * 2;
            float2 v0 = make_float2(acc[mt][nt][0], acc[mt][nt][1]);
            float2 v1 = make_float2(acc[mt][nt][2], acc[mt][nt][3]);
            *(float2*)&C[(size_t)row * Ncol + col] = v0;
            *(float2*)&C[(size_t)(row + 8) * Ncol + col] = v1;
        }
    }
}

// ===========================================================================
// Quantize GEMM output rows to biased uint16 with per-row scale.
// One block per row, NCOL/4 threads, 4 cols per thread.
// ===========================================================================
template <int NCOL>
__global__ __launch_bounds__(NCOL / 4) void k_quant(const float* __restrict__ src,
                                                    unsigned short* __restrict__ q,
                                                    float* __restrict__ qs) {
    constexpr int T = NCOL / 4;
    int row = blockIdx.x;
    int tid = threadIdx.x;
    __shared__ float s_max[T / 32];

    float4 v = ((const float4*)src)[(size_t)row * T + tid];
    float m = fmaxf(fmaxf(fabsf(v.x), fabsf(v.y)), fmaxf(fabsf(v.z), fabsf(v.w)));
#pragma unroll
    for (int d = 16; d > 0; d >>= 1)
        m = fmaxf(m, __shfl_xor_sync(0xFFFFFFFFu, m, d));
    if ((tid & 31) == 0) s_max[tid >> 5] = m;
    __syncthreads();
    float mx = s_max[0];
#pragma unroll
    for (int i = 1; i < T / 32; i++) mx = fmaxf(mx, s_max[i]);

    float inv = (mx > 0.0f) ? (32767.0f / mx) : 0.0f;
    float s   = (mx > 0.0f) ? (mx / 32767.0f) : 0.0f;

    ushort4 r;
    r.x = (unsigned short)(__float2int_rn(v.x * inv) + 32768);
    r.y = (unsigned short)(__float2int_rn(v.y * inv) + 32768);
    r.z = (unsigned short)(__float2int_rn(v.z * inv) + 32768);
    r.w = (unsigned short)(__float2int_rn(v.w * inv) + 32768);
    ((ushort4*)q)[(size_t)row * T + tid] = r;
    if (tid == 0) qs[row] = s;
}

// ===========================================================================
// SpMM with int16 gather:
// out[row] = act( dinv_r*( selfcoef_r*tmpf[row] + sum_j (dinv_j*s_j)*deq(q_j) ) + b )
// deq via PRMT magic: f = as_float(0x4B000000|u16) - 8421376  (exact integer)
// ===========================================================================
#define QMAGIC 8421376.0f   // 8388608 + 32768

__device__ __forceinline__ void deq_fma(float4& a, float w, uint2 u) {
    uint32_t p0 = __byte_perm(u.x, 0x4B000000u, 0x7410);
    uint32_t p1 = __byte_perm(u.x, 0x4B000000u, 0x7432);
    uint32_t p2 = __byte_perm(u.y, 0x4B000000u, 0x7410);
    uint32_t p3 = __byte_perm(u.y, 0x4B000000u, 0x7432);
    a.x += w * (__uint_as_float(p0) - QMAGIC);
    a.y += w * (__uint_as_float(p1) - QMAGIC);
    a.z += w * (__uint_as_float(p2) - QMAGIC);
    a.w += w * (__uint_as_float(p3) - QMAGIC);
}

template <int NCOL, bool RELU>
__global__ __launch_bounds__(NCOL / 4) void k_spmm(const float* __restrict__ tmpf,
                                                   const unsigned short* __restrict__ q,
                                                   const float* __restrict__ qs,
                                                   const float* __restrict__ bias,
                                                   float* __restrict__ out) {
    constexpr int T = NCOL / 4;
    int row = blockIdx.x;
    int tid = threadIdx.x;

    __shared__ int   s_cols[MAXDEG];
    __shared__ float s_w[MAXDEG];

    int n = g_cnt[row];
    for (int t = tid; t < n; t += T) {
        int j = g_cols[(size_t)row * MAXDEG + t];
        s_cols[t] = j;
        s_w[t] = g_dinv[j] * qs[j];
    }
    __syncthreads();

    // self term in exact fp32
    float4 acc = ((const float4*)tmpf)[(size_t)row * T + tid];
    float sc = g_selfcoef[row];
    acc.x *= sc; acc.y *= sc; acc.z *= sc; acc.w *= sc;

    const uint2* qp = (const uint2*)q;
    int t = 0;
    for (; t + 4 <= n; t += 4) {
        int j0 = s_cols[t], j1 = s_cols[t + 1], j2 = s_cols[t + 2], j3 = s_cols[t + 3];
        float w0 = s_w[t], w1 = s_w[t + 1], w2 = s_w[t + 2], w3 = s_w[t + 3];
        uint2 u0 = qp[(size_t)j0 * T + tid];
        uint2 u1 = qp[(size_t)j1 * T + tid];
        uint2 u2 = qp[(size_t)j2 * T + tid];
        uint2 u3 = qp[(size_t)j3 * T + tid];
        deq_fma(acc, w0, u0); deq_fma(acc, w1, u1);
        deq_fma(acc, w2, u2); deq_fma(acc, w3, u3);
    }
    for (; t < n; t++) {
        uint2 u = qp[(size_t)s_cols[t] * T + tid];
        deq_fma(acc, s_w[t], u);
    }

    float di = g_dinv[row];
    float4 bv = ((const float4*)bias)[tid];
    float4 r;
    r.x = di * acc.x + bv.x;
    r.y = di * acc.y + bv.y;
    r.z = di * acc.z + bv.z;
    r.w = di * acc.w + bv.w;
    if (RELU) {
        r.x = fmaxf(r.x, 0.0f); r.y = fmaxf(r.y, 0.0f);
        r.z = fmaxf(r.z, 0.0f); r.w = fmaxf(r.w, 0.0f);
    }
    ((float4*)out)[(size_t)row * T + tid] = r;
}

// ===========================================================================
extern "C" void kernel_launch(void* const* d_in, const int* in_sizes, int n_in,
                              void* d_out, int out_size) {
    const float* x  = (const float*)d_in[0];
    const int*   ei = (const int*)d_in[1];
    const float* W1 = (const float*)d_in[2];
    const float* b1 = (const float*)d_in[3];
    const float* W2 = (const float*)d_in[4];
    const float* b2 = (const float*)d_in[5];
    const float* W3 = (const float*)d_in[6];
    const float* b3 = (const float*)d_in[7];
    float* out = (float*)d_out;

    int E = in_sizes[1] / 2;

    void *p0, *p1, *pa, *pb, *pq, *pqs;
    cudaGetSymbolAddress(&p0, g_buf0);
    cudaGetSymbolAddress(&p1, g_buf1);
    cudaGetSymbolAddress(&pa, g_abf);
    cudaGetSymbolAddress(&pb, g_bbf);
    cudaGetSymbolAddress(&pq, g_q);
    cudaGetSymbolAddress(&pqs, g_qs);
    float* buf0 = (float*)p0;
    float* buf1 = (float*)p1;
    __nv_bfloat16* abf = (__nv_bfloat16*)pa;
    __nv_bfloat16* bbf = (__nv_bfloat16*)pb;
    unsigned short* qb = (unsigned short*)pq;
    float* qsb = (float*)pqs;

    // --- graph build ---
    k_clear_bits<<<NNODES * WORDS_PER_ROW / 256, 256>>>();
    k_detect<<<(E + 255) / 256, 256>>>(ei, 2 * E);
    k_scatter<<<(E + 255) / 256, 256>>>(ei, E);
    k_build_rows<<<NNODES / 8, 256>>>();

    dim3 g512(512 / 128, NNODES / 128);
    dim3 g256(256 / 128, NNODES / 128);
    int nA = NNODES * 512 / 256;

    // layer 1
    k_expandA<<<nA, 256>>>(x, abf);
    k_expandB<<<(512 * 512 + 255) / 256, 256>>>(W1, bbf, 512);
    k_gemm_mma<<<g512, 256>>>(abf, bbf, buf0, 512);
    k_quant<512><<<NNODES, 128>>>(buf0, qb, qsb);
    k_spmm<512, true><<<NNODES, 128>>>(buf0, qb, qsb, b1, buf1);

    // layer 2
    k_expandA<<<nA, 256>>>(buf1, abf);
    k_expandB<<<(512 * 512 + 255) / 256, 256>>>(W2, bbf, 512);
    k_gemm_mma<<<g512, 256>>>(abf, bbf, buf0, 512);
    k_quant<512><<<NNODES, 128>>>(buf0, qb, qsb);
    k_spmm<512, true><<<NNODES, 128>>>(buf0, qb, qsb, b2, buf1);

    // layer 3
    k_expandA<<<nA, 256>>>(buf1, abf);
    k_expandB<<<(256 * 512 + 255) / 256, 256>>>(W3, bbf, 256);
    k_gemm_mma<<<g256, 256>>>(abf, bbf, buf0, 256);
    k_quant<256><<<NNODES, 64>>>(buf0, qb, qsb);
    k_spmm<256, false><<<NNODES, 64>>>(buf0, qb, qsb, b3, out);
}

// round 6
// speedup vs baseline: 1.2175x; 1.2175x over previous
#include <cuda_runtime.h>
#include <cuda_bf16.h>
#include <cstdint>

// ===========================================================================
// GCN: out = Anorm @ relu(Anorm @ relu(Anorm @ (x W1) + b1) W2 + b2) W3 + b3
// GEMM: bf16 mma.sync, 3-term split (ah*bh + ah*bl + al*bh) fused in-kernel
//       from fp32 A tiles; ldmatrix fragments; epilogue emits int16 + scales.
// SpMM: int16 gather with exact PRMT/FADD dequant.
// ===========================================================================

#define NNODES 8192
#define FDIM   512
#define WORDS_PER_ROW 256
#define MAXDEG 192

__device__ unsigned int g_bits[NNODES * WORDS_PER_ROW];   // 8 MB
__device__ unsigned int g_self[WORDS_PER_ROW];
__device__ float g_dinv[NNODES];
__device__ float g_selfcoef[NNODES];
__device__ int   g_cols[NNODES * MAXDEG];
__device__ int   g_cnt[NNODES];
__device__ int   g_is64;
__device__ float g_buf0[NNODES * FDIM];                   // activations ping
__device__ float g_buf1[NNODES * FDIM];                   // activations pong
__device__ __nv_bfloat16 g_bh[512 * 512];                 // W high part, n-major
__device__ __nv_bfloat16 g_bl[512 * 512];                 // W low  part, n-major
__device__ unsigned short g_q[NNODES * FDIM];             // quantized GEMM out
__device__ float g_qs[NNODES * 4];                        // per-(row,128col) scale

// ===========================================================================
// Graph build
// ===========================================================================
__global__ void k_clear_bits() {
    int idx = blockIdx.x * blockDim.x + threadIdx.x;
    int row = idx >> 8;
    int w   = idx & 255;
    g_bits[idx] = (w == (row >> 5)) ? (1u << (row & 31)) : 0u;
    if (idx < WORDS_PER_ROW) g_self[idx] = 0u;
    if (idx == 0) g_is64 = 1;
}

__global__ void k_detect(const int* __restrict__ w, int nwords) {
    int i = blockIdx.x * blockDim.x + threadIdx.x;
    int idx = 2 * i + 1;
    if (idx < nwords && w[idx] != 0) g_is64 = 0;
}

__global__ void k_scatter(const int* __restrict__ w, int E) {
    int i = blockIdx.x * blockDim.x + threadIdx.x;
    if (i >= E) return;
    int a, b;
    if (g_is64) { a = w[2 * i]; b = w[2 * E + 2 * i]; }
    else        { a = w[i];     b = w[E + i]; }
    if ((unsigned)a >= NNODES || (unsigned)b >= NNODES) return;
    atomicOr(&g_bits[(size_t)a * WORDS_PER_ROW + (b >> 5)], 1u << (b & 31));
    atomicOr(&g_bits[(size_t)b * WORDS_PER_ROW + (a >> 5)], 1u << (a & 31));
    if (a == b) atomicOr(&g_self[a >> 5], 1u << (a & 31));
}

__global__ void k_build_rows() {
    int warp = (blockIdx.x * blockDim.x + threadIdx.x) >> 5;
    int lane = threadIdx.x & 31;
    if (warp >= NNODES) return;
    int row = warp;

    unsigned int w[8];
    const unsigned int* base = &g_bits[(size_t)row * WORDS_PER_ROW + lane * 8];
#pragma unroll
    for (int t = 0; t < 8; t++) w[t] = base[t];

    int dw = row >> 5;
    if ((dw >> 3) == lane) w[dw & 7] &= ~(1u << (row & 31));

    unsigned int cnt = 0;
#pragma unroll
    for (int t = 0; t < 8; t++) cnt += __popc(w[t]);

    unsigned int incl = cnt;
#pragma unroll
    for (int d = 1; d < 32; d <<= 1) {
        unsigned int v = __shfl_up_sync(0xFFFFFFFFu, incl, d);
        if (lane >= d) incl += v;
    }
    unsigned int excl  = incl - cnt;
    unsigned int total = __shfl_sync(0xFFFFFFFFu, incl, 31);

    int* cols = &g_cols[(size_t)row * MAXDEG];
    unsigned int o = excl;
#pragma unroll
    for (int t = 0; t < 8; t++) {
        unsigned int bits = w[t];
        int colbase = (lane * 8 + t) * 32;
        while (bits) {
            int b = __ffs(bits) - 1;
            bits &= bits - 1;
            if (o < MAXDEG) cols[o] = colbase + b;
            o++;
        }
    }

    if (lane == 0) {
        int self = (g_self[row >> 5] >> (row & 31)) & 1;
        float deg = (float)total + 1.0f + (float)self;
        float di = rsqrtf(deg);
        g_dinv[row] = di;
        g_selfcoef[row] = (1.0f + (float)self) * di;
        g_cnt[row] = (int)(total < MAXDEG ? total : MAXDEG);
    }
}

// ===========================================================================
// W split: bh/bl [Ncol x 512] n-major from W [512 x Ncol]
// ===========================================================================
__global__ void k_expandB(const float* __restrict__ W, __nv_bfloat16* __restrict__ bh,
                          __nv_bfloat16* __restrict__ bl, int Ncol) {
    int idx = blockIdx.x * blockDim.x + threadIdx.x;
    if (idx >= Ncol * 512) return;
    int n = idx >> 9;
    int k = idx & 511;
    float v = W[(size_t)k * Ncol + n];
    __nv_bfloat16 hi = __float2bfloat16_rn(v);
    __nv_bfloat16 lo = __float2bfloat16_rn(v - __bfloat162float(hi));
    bh[(size_t)n * 512 + k] = hi;
    bl[(size_t)n * 512 + k] = lo;
}

// ===========================================================================
// Fused split GEMM + int16 quantizing epilogue.
// C = A @ W done as ah*bh + ah*bl + al*bh on tensor cores.
// CTA 128x128, 8 warps (2m x 4n), warp tile 64x32, K chunks of 32.
// SMEM row stride 40 bf16 (80 B) -> conflict-free LDSM.
// ===========================================================================
#define SM_AH 0
#define SM_AL 10240
#define SM_BH0 20480
#define SM_BL0 30720
#define SM_BH1 40960
#define SM_BL1 51200
#define SM_TOT 61440
#define QMAGICF 8421376.0f    // 2^23 + 32768

__device__ __forceinline__ void cp16(uint32_t saddr, const void* g) {
    asm volatile("cp.async.cg.shared.global [%0], [%1], 16;" :: "r"(saddr), "l"(g));
}
__device__ __forceinline__ void cp_commit() { asm volatile("cp.async.commit_group;"); }
template <int N> __device__ __forceinline__ void cp_wait() {
    asm volatile("cp.async.wait_group %0;" :: "n"(N));
}
__device__ __forceinline__ void ldsm4(uint32_t& r0, uint32_t& r1, uint32_t& r2,
                                      uint32_t& r3, uint32_t addr) {
    asm volatile("ldmatrix.sync.aligned.m8n8.x4.shared.b16 {%0,%1,%2,%3}, [%4];"
                 : "=r"(r0), "=r"(r1), "=r"(r2), "=r"(r3) : "r"(addr));
}
__device__ __forceinline__ void mma16816(float* c, uint32_t a0, uint32_t a1,
                                         uint32_t a2, uint32_t a3,
                                         uint32_t b0, uint32_t b1) {
    asm volatile(
        "mma.sync.aligned.m16n8k16.row.col.f32.bf16.bf16.f32 "
        "{%0,%1,%2,%3}, {%4,%5,%6,%7}, {%8,%9}, {%0,%1,%2,%3};"
        : "+f"(c[0]), "+f"(c[1]), "+f"(c[2]), "+f"(c[3])
        : "r"(a0), "r"(a1), "r"(a2), "r"(a3), "r"(b0), "r"(b1));
}
__device__ __forceinline__ uint32_t packbf2(float x, float y) {
    __nv_bfloat162 t = __floats2bfloat162_rn(x, y);
    return *(uint32_t*)&t;
}

__global__ __launch_bounds__(256) void k_gemm_fused(
    const float* __restrict__ A,           // [8192 x 512] fp32 (row-major)
    const __nv_bfloat16* __restrict__ Bh,  // [Ncol x 512]
    const __nv_bfloat16* __restrict__ Bl,
    unsigned short* __restrict__ Q,        // [8192 x Ncol]
    float* __restrict__ QS,                // [8192 x 4]
    int Ncol)
{
    extern __shared__ char sm[];
    const uint32_t sb = (uint32_t)__cvta_generic_to_shared(sm);

    int tid = threadIdx.x, wid = tid >> 5, lane = tid & 31;
    int g = lane >> 2, tig = lane & 3;
    int m0 = blockIdx.y * 128, n0 = blockIdx.x * 128;
    int wm = (wid >> 2) * 64, wn = (wid & 3) * 32;

    // A load mapping: thread covers rows r0+32i, cols c4*4..+3 (fp32)
    int r0 = tid >> 3, c4a = tid & 7;
    // B cp.async mapping: 2 chunks of 16B per tensor: n = c>>2, c4 = c&3
    int bn0 = tid >> 2, bc0 = (tid & 3) * 16;            // chunk tid
    int bn1 = (tid + 256) >> 2, bc1 = (tid & 3) * 16;    // chunk tid+256 (same c4 bits)

    const float* Ab = A + (size_t)m0 * 512;
    const __nv_bfloat16* Bhb = Bh + (size_t)n0 * 512;
    const __nv_bfloat16* Blb = Bl + (size_t)n0 * 512;

    const uint32_t BHo[2] = {sb + SM_BH0, sb + SM_BH1};
    const uint32_t BLo[2] = {sb + SM_BL0, sb + SM_BL1};

    // ldmatrix base offsets (bytes)
    uint32_t a_base = (uint32_t)((wm + (lane & 7) + ((lane >> 3) & 1) * 8) * 80
                                 + ((lane >> 4) & 1) * 16);
    uint32_t b_base = (uint32_t)((wn + (lane & 7) + ((lane >> 4) & 1) * 8) * 80
                                 + ((lane >> 3) & 1) * 16);

    float acc[4][4][4];
#pragma unroll
    for (int mt = 0; mt < 4; mt++)
#pragma unroll
        for (int nt = 0; nt < 4; nt++)
#pragma unroll
            for (int j = 0; j < 4; j++) acc[mt][nt][j] = 0.0f;

    float4 av[4];

    // ---- prologue: B chunk0 via cp.async, A chunk0 via regs+STS ----
    {
        cp16(BHo[0] + bn0 * 80 + bc0, Bhb + (size_t)bn0 * 512 + bc0 / 2);
        cp16(BHo[0] + bn1 * 80 + bc1, Bhb + (size_t)bn1 * 512 + bc1 / 2);
        cp16(BLo[0] + bn0 * 80 + bc0, Blb + (size_t)bn0 * 512 + bc0 / 2);
        cp16(BLo[0] + bn1 * 80 + bc1, Blb + (size_t)bn1 * 512 + bc1 / 2);
        cp_commit();
#pragma unroll
        for (int i = 0; i < 4; i++)
            av[i] = *(const float4*)(Ab + (size_t)(r0 + 32 * i) * 512 + c4a * 4);
#pragma unroll
        for (int i = 0; i < 4; i++) {
            int off = (r0 + 32 * i) * 80 + c4a * 8;
            float hx = __bfloat162float(__float2bfloat16_rn(av[i].x));
            float hy = __bfloat162float(__float2bfloat16_rn(av[i].y));
            float hz = __bfloat162float(__float2bfloat16_rn(av[i].z));
            float hw = __bfloat162float(__float2bfloat16_rn(av[i].w));
            *(uint2*)(sm + SM_AH + off) = make_uint2(packbf2(av[i].x, av[i].y),
                                                    packbf2(av[i].z, av[i].w));
            *(uint2*)(sm + SM_AL + off) = make_uint2(packbf2(av[i].x - hx, av[i].y - hy),
                                                    packbf2(av[i].z - hz, av[i].w - hw));
        }
    }

    for (int k = 0; k < 16; k++) {
        int buf = k & 1;
        if (k < 15) {
            int k0 = (k + 1) * 32;
            int nb = buf ^ 1;
            cp16(BHo[nb] + bn0 * 80 + bc0, Bhb + (size_t)bn0 * 512 + k0 + bc0 / 2);
            cp16(BHo[nb] + bn1 * 80 + bc1, Bhb + (size_t)bn1 * 512 + k0 + bc1 / 2);
            cp16(BLo[nb] + bn0 * 80 + bc0, Blb + (size_t)bn0 * 512 + k0 + bc0 / 2);
            cp16(BLo[nb] + bn1 * 80 + bc1, Blb + (size_t)bn1 * 512 + k0 + bc1 / 2);
            cp_commit();
#pragma unroll
            for (int i = 0; i < 4; i++)
                av[i] = *(const float4*)(Ab + (size_t)(r0 + 32 * i) * 512 + k0 + c4a * 4);
            cp_wait<1>();
        } else {
            cp_wait<0>();
        }
        __syncthreads();

#pragma unroll
        for (int ks2 = 0; ks2 < 2; ks2++) {
            uint32_t ksb = ks2 * 32;
            uint32_t bh[4][2], bl[4][2];
#pragma unroll
            for (int p = 0; p < 2; p++) {
                ldsm4(bh[2 * p][0], bh[2 * p][1], bh[2 * p + 1][0], bh[2 * p + 1][1],
                      BHo[buf] + b_base + p * 1280 + ksb);
                ldsm4(bl[2 * p][0], bl[2 * p][1], bl[2 * p + 1][0], bl[2 * p + 1][1],
                      BLo[buf] + b_base + p * 1280 + ksb);
            }
#pragma unroll
            for (int mt = 0; mt < 4; mt++) {
                uint32_t ah0, ah1, ah2, ah3, al0, al1, al2, al3;
                ldsm4(ah0, ah1, ah2, ah3, sb + SM_AH + a_base + mt * 1280 + ksb);
                ldsm4(al0, al1, al2, al3, sb + SM_AL + a_base + mt * 1280 + ksb);
#pragma unroll
                for (int nt = 0; nt < 4; nt++) {
                    mma16816(acc[mt][nt], ah0, ah1, ah2, ah3, bh[nt][0], bh[nt][1]);
                    mma16816(acc[mt][nt], ah0, ah1, ah2, ah3, bl[nt][0], bl[nt][1]);
                    mma16816(acc[mt][nt], al0, al1, al2, al3, bh[nt][0], bh[nt][1]);
                }
            }
        }
        __syncthreads();

        if (k < 15) {
#pragma unroll
            for (int i = 0; i < 4; i++) {
                int off = (r0 + 32 * i) * 80 + c4a * 8;
                float hx = __bfloat162float(__float2bfloat16_rn(av[i].x));
                float hy = __bfloat162float(__float2bfloat16_rn(av[i].y));
                float hz = __bfloat162float(__float2bfloat16_rn(av[i].z));
                float hw = __bfloat162float(__float2bfloat16_rn(av[i].w));
                *(uint2*)(sm + SM_AH + off) = make_uint2(packbf2(av[i].x, av[i].y),
                                                        packbf2(av[i].z, av[i].w));
                *(uint2*)(sm + SM_AL + off) = make_uint2(packbf2(av[i].x - hx, av[i].y - hy),
                                                        packbf2(av[i].z - hz, av[i].w - hw));
            }
        }
    }

    // ---- epilogue: per-(row, CTA-block) max -> scale -> int16 stores ----
    __syncthreads();
    float* s_rm = (float*)sm;    // [128][4]

    float rmax[4][2];
#pragma unroll
    for (int mt = 0; mt < 4; mt++)
#pragma unroll
        for (int h = 0; h < 2; h++) {
            float m = 0.0f;
#pragma unroll
            for (int nt = 0; nt < 4; nt++)
                m = fmaxf(m, fmaxf(fabsf(acc[mt][nt][2 * h]), fabsf(acc[mt][nt][2 * h + 1])));
            m = fmaxf(m, __shfl_xor_sync(0xFFFFFFFFu, m, 1));
            m = fmaxf(m, __shfl_xor_sync(0xFFFFFFFFu, m, 2));
            rmax[mt][h] = m;
        }
    if (tig == 0) {
#pragma unroll
        for (int mt = 0; mt < 4; mt++)
#pragma unroll
            for (int h = 0; h < 2; h++)
                s_rm[(wm + mt * 16 + g + 8 * h) * 4 + (wid & 3)] = rmax[mt][h];
    }
    __syncthreads();

#pragma unroll
    for (int mt = 0; mt < 4; mt++)
#pragma unroll
        for (int h = 0; h < 2; h++) {
            int rl = wm + mt * 16 + g + 8 * h;
            float mx = fmaxf(fmaxf(s_rm[rl * 4 + 0], s_rm[rl * 4 + 1]),
                             fmaxf(s_rm[rl * 4 + 2], s_rm[rl * 4 + 3]));
            float inv = (mx > 0.0f) ? (32766.0f / mx) : 0.0f;
            if ((wid & 3) == 0 && tig == 0)
                QS[(size_t)(m0 + rl) * 4 + blockIdx.x] = mx * (1.0f / 32766.0f);
            size_t rowoff = (size_t)(m0 + rl) * Ncol + n0 + wn;
#pragma unroll
            for (int nt = 0; nt < 4; nt++) {
                uint32_t u0 = __float_as_uint(fmaf(acc[mt][nt][2 * h], inv, QMAGICF));
                uint32_t u1 = __float_as_uint(fmaf(acc[mt][nt][2 * h + 1], inv, QMAGICF));
                *(uint32_t*)&Q[rowoff + nt * 8 + tig * 2] = __byte_perm(u0, u1, 0x5410);
            }
        }
}

// ===========================================================================
// SpMM with int16 gather + exact dequant.
// ===========================================================================
__device__ __forceinline__ void deq_fma(float4& a, float w, uint2 u) {
    uint32_t p0 = __byte_perm(u.x, 0x4B000000u, 0x7410);
    uint32_t p1 = __byte_perm(u.x, 0x4B000000u, 0x7432);
    uint32_t p2 = __byte_perm(u.y, 0x4B000000u, 0x7410);
    uint32_t p3 = __byte_perm(u.y, 0x4B000000u, 0x7432);
    a.x += w * (__uint_as_float(p0) - QMAGICF);
    a.y += w * (__uint_as_float(p1) - QMAGICF);
    a.z += w * (__uint_as_float(p2) - QMAGICF);
    a.w += w * (__uint_as_float(p3) - QMAGICF);
}

template <int NCOL, int NB, bool RELU>
__global__ __launch_bounds__(NCOL / 4) void k_spmm(const unsigned short* __restrict__ q,
                                                   const float* __restrict__ qs,
                                                   const float* __restrict__ bias,
                                                   float* __restrict__ out) {
    constexpr int T = NCOL / 4;
    int row = blockIdx.x;
    int tid = threadIdx.x;

    __shared__ int   s_cols[MAXDEG];
    __shared__ float s_w[MAXDEG * NB];

    int n = g_cnt[row];
    for (int t = tid; t < n; t += T) {
        int j = g_cols[(size_t)row * MAXDEG + t];
        s_cols[t] = j;
        float dj = g_dinv[j];
#pragma unroll
        for (int b = 0; b < NB; b++) s_w[t * NB + b] = dj * qs[(size_t)j * 4 + b];
    }
    __syncthreads();

    int nb = tid >> 5;
    const uint2* qp = (const uint2*)q;

    float4 acc = make_float4(0.0f, 0.0f, 0.0f, 0.0f);
    {   // self term (also int16; weight = selfcoef * scale)
        float ws = g_selfcoef[row] * qs[(size_t)row * 4 + nb];
        deq_fma(acc, ws, qp[(size_t)row * T + tid]);
    }

    int t = 0;
    for (; t + 8 <= n; t += 8) {
        uint2 u[8];
        float w[8];
#pragma unroll
        for (int i = 0; i < 8; i++) {
            int j = s_cols[t + i];
            w[i] = s_w[(t + i) * NB + nb];
            u[i] = qp[(size_t)j * T + tid];
        }
#pragma unroll
        for (int i = 0; i < 8; i++) deq_fma(acc, w[i], u[i]);
    }
    for (; t < n; t++) {
        uint2 u = qp[(size_t)s_cols[t] * T + tid];
        deq_fma(acc, s_w[t * NB + nb], u);
    }

    float di = g_dinv[row];
    float4 bv = ((const float4*)bias)[tid];
    float4 r;
    r.x = di * acc.x + bv.x;
    r.y = di * acc.y + bv.y;
    r.z = di * acc.z + bv.z;
    r.w = di * acc.w + bv.w;
    if (RELU) {
        r.x = fmaxf(r.x, 0.0f); r.y = fmaxf(r.y, 0.0f);
        r.z = fmaxf(r.z, 0.0f); r.w = fmaxf(r.w, 0.0f);
    }
    ((float4*)out)[(size_t)row * T + tid] = r;
}

// ===========================================================================
extern "C" void kernel_launch(void* const* d_in, const int* in_sizes, int n_in,
                              void* d_out, int out_size) {
    const float* x  = (const float*)d_in[0];
    const int*   ei = (const int*)d_in[1];
    const float* W1 = (const float*)d_in[2];
    const float* b1 = (const float*)d_in[3];
    const float* W2 = (const float*)d_in[4];
    const float* b2 = (const float*)d_in[5];
    const float* W3 = (const float*)d_in[6];
    const float* b3 = (const float*)d_in[7];
    float* out = (float*)d_out;

    int E = in_sizes[1] / 2;

    void *p0, *p1, *ph, *pl, *pq, *pqs;
    cudaGetSymbolAddress(&p0, g_buf0);
    cudaGetSymbolAddress(&p1, g_buf1);
    cudaGetSymbolAddress(&ph, g_bh);
    cudaGetSymbolAddress(&pl, g_bl);
    cudaGetSymbolAddress(&pq, g_q);
    cudaGetSymbolAddress(&pqs, g_qs);
    float* buf0 = (float*)p0;
    float* buf1 = (float*)p1;
    __nv_bfloat16* bh = (__nv_bfloat16*)ph;
    __nv_bfloat16* bl = (__nv_bfloat16*)pl;
    unsigned short* qb = (unsigned short*)pq;
    float* qsb = (float*)pqs;

    cudaFuncSetAttribute(k_gemm_fused, cudaFuncAttributeMaxDynamicSharedMemorySize, SM_TOT);

    // --- graph build ---
    k_clear_bits<<<NNODES * WORDS_PER_ROW / 256, 256>>>();
    k_detect<<<(E + 255) / 256, 256>>>(ei, 2 * E);
    k_scatter<<<(E + 255) / 256, 256>>>(ei, E);
    k_build_rows<<<NNODES / 8, 256>>>();

    dim3 g512(4, 64);
    dim3 g256(2, 64);

    // layer 1: x -> buf0
    k_expandB<<<(512 * 512 + 255) / 256, 256>>>(W1, bh, bl, 512);
    k_gemm_fused<<<g512, 256, SM_TOT>>>(x, bh, bl, qb, qsb, 512);
    k_spmm<512, 4, true><<<NNODES, 128>>>(qb, qsb, b1, buf0);

    // layer 2: buf0 -> buf1
    k_expandB<<<(512 * 512 + 255) / 256, 256>>>(W2, bh, bl, 512);
    k_gemm_fused<<<g512, 256, SM_TOT>>>(buf0, bh, bl, qb, qsb, 512);
    k_spmm<512, 4, true><<<NNODES, 128>>>(qb, qsb, b2, buf1);

    // layer 3: buf1 -> out
    k_expandB<<<(256 * 512 + 255) / 256, 256>>>(W3, bh, bl, 256);
    k_gemm_fused<<<g256, 256, SM_TOT>>>(buf1, bh, bl, qb, qsb, 256);
    k_spmm<256, 2, false><<<NNODES, 64>>>(qb, qsb, b3, out);
}

// round 7
// speedup vs baseline: 1.3053x; 1.0721x over previous
#include <cuda_runtime.h>
#include <cuda_bf16.h>
#include <cstdint>

// ===========================================================================
// GCN: out = Anorm @ relu(Anorm @ relu(Anorm @ (x W1) + b1) W2 + b2) W3 + b3
// Activations carried as bf16 (hi,lo) split pairs. GEMM: bf16 mma.sync,
// 3-term split, all-cp.async pipeline, int16-quantizing epilogue.
// SpMM: int16 gather, exact PRMT/FADD dequant, emits bf16 split (or fp32 out).
// ===========================================================================

#define NNODES 8192
#define FDIM   512
#define WORDS_PER_ROW 256
#define MAXDEG 192
#define QMAGICF 8421376.0f    // 2^23 + 32768

__device__ unsigned int g_bits[NNODES * WORDS_PER_ROW];   // 8 MB
__device__ unsigned int g_self[WORDS_PER_ROW];
__device__ float g_dinv[NNODES];
__device__ float g_selfcoef[NNODES];
__device__ int   g_cols[NNODES * MAXDEG];
__device__ int   g_cnt[NNODES];
__device__ int   g_is64;
__device__ __nv_bfloat16 g_ah[NNODES * FDIM];             // 8 MB activation hi
__device__ __nv_bfloat16 g_al[NNODES * FDIM];             // 8 MB activation lo
// W splits for all 3 layers: [0]=W1(512x512), [262144]=W2, [524288]=W3(256x512)
__device__ __nv_bfloat16 g_bh[655360];
__device__ __nv_bfloat16 g_bl[655360];
__device__ unsigned short g_q[NNODES * FDIM];             // quantized GEMM out
__device__ float g_qs[NNODES * 4];                        // per-(row,128col) scale

// ===========================================================================
// Graph build
// ===========================================================================
__global__ void k_clear_detect(const int* __restrict__ ei, int E) {
    int idx = blockIdx.x * blockDim.x + threadIdx.x;
    int row = idx >> 8;
    int w   = idx & 255;
    g_bits[idx] = (w == (row >> 5)) ? (1u << (row & 31)) : 0u;
    if (idx < WORDS_PER_ROW) g_self[idx] = 0u;
    if (idx == 0) g_is64 = 1;
    // int64 detection: odd 32-bit words of the first 2E words are all zero
    if (idx < E) {
        if (ei[2 * idx + 1] != 0) g_is64 = 0;
    }
}

__global__ void k_scatter(const int* __restrict__ w, int E) {
    int i = blockIdx.x * blockDim.x + threadIdx.x;
    if (i >= E) return;
    int a, b;
    if (g_is64) { a = w[2 * i]; b = w[2 * E + 2 * i]; }
    else        { a = w[i];     b = w[E + i]; }
    if ((unsigned)a >= NNODES || (unsigned)b >= NNODES) return;
    atomicOr(&g_bits[(size_t)a * WORDS_PER_ROW + (b >> 5)], 1u << (b & 31));
    atomicOr(&g_bits[(size_t)b * WORDS_PER_ROW + (a >> 5)], 1u << (a & 31));
    if (a == b) atomicOr(&g_self[a >> 5], 1u << (a & 31));
}

__global__ void k_build_rows() {
    int warp = (blockIdx.x * blockDim.x + threadIdx.x) >> 5;
    int lane = threadIdx.x & 31;
    if (warp >= NNODES) return;
    int row = warp;

    unsigned int w[8];
    const unsigned int* base = &g_bits[(size_t)row * WORDS_PER_ROW + lane * 8];
#pragma unroll
    for (int t = 0; t < 8; t++) w[t] = base[t];

    int dw = row >> 5;
    if ((dw >> 3) == lane) w[dw & 7] &= ~(1u << (row & 31));

    unsigned int cnt = 0;
#pragma unroll
    for (int t = 0; t < 8; t++) cnt += __popc(w[t]);

    unsigned int incl = cnt;
#pragma unroll
    for (int d = 1; d < 32; d <<= 1) {
        unsigned int v = __shfl_up_sync(0xFFFFFFFFu, incl, d);
        if (lane >= d) incl += v;
    }
    unsigned int excl  = incl - cnt;
    unsigned int total = __shfl_sync(0xFFFFFFFFu, incl, 31);

    int* cols = &g_cols[(size_t)row * MAXDEG];
    unsigned int o = excl;
#pragma unroll
    for (int t = 0; t < 8; t++) {
        unsigned int bits = w[t];
        int colbase = (lane * 8 + t) * 32;
        while (bits) {
            int b = __ffs(bits) - 1;
            bits &= bits - 1;
            if (o < MAXDEG) cols[o] = colbase + b;
            o++;
        }
    }

    if (lane == 0) {
        int self = (g_self[row >> 5] >> (row & 31)) & 1;
        float deg = (float)total + 1.0f + (float)self;
        float di = rsqrtf(deg);
        g_dinv[row] = di;
        g_selfcoef[row] = (1.0f + (float)self) * di;
        g_cnt[row] = (int)(total < MAXDEG ? total : MAXDEG);
    }
}

// ===========================================================================
// expandX: x fp32 -> (ah, al) bf16 split
// ===========================================================================
__device__ __forceinline__ uint32_t packbf2(float x, float y) {
    __nv_bfloat162 t = __floats2bfloat162_rn(x, y);
    return *(uint32_t*)&t;
}

__global__ void k_expandX(const float* __restrict__ X,
                          __nv_bfloat16* __restrict__ ah,
                          __nv_bfloat16* __restrict__ al) {
    int idx = blockIdx.x * blockDim.x + threadIdx.x;   // over (8192*512)/4
    float4 v = ((const float4*)X)[idx];
    float hx = __bfloat162float(__float2bfloat16_rn(v.x));
    float hy = __bfloat162float(__float2bfloat16_rn(v.y));
    float hz = __bfloat162float(__float2bfloat16_rn(v.z));
    float hw = __bfloat162float(__float2bfloat16_rn(v.w));
    ((uint2*)ah)[idx] = make_uint2(packbf2(v.x, v.y), packbf2(v.z, v.w));
    ((uint2*)al)[idx] = make_uint2(packbf2(v.x - hx, v.y - hy), packbf2(v.z - hz, v.w - hw));
}

// ===========================================================================
// expandB_all: W1, W2 (512x512), W3 (512x256) -> n-major bf16 hi/lo
// ===========================================================================
__global__ void k_expandB_all(const float* __restrict__ W1, const float* __restrict__ W2,
                              const float* __restrict__ W3) {
    int idx = blockIdx.x * blockDim.x + threadIdx.x;   // over 655360
    if (idx >= 655360) return;
    const float* W;
    int Ncol, local;
    if (idx < 262144)      { W = W1; Ncol = 512; local = idx; }
    else if (idx < 524288) { W = W2; Ncol = 512; local = idx - 262144; }
    else                   { W = W3; Ncol = 256; local = idx - 524288; }
    int n = local >> 9;
    int k = local & 511;
    float v = W[(size_t)k * Ncol + n];
    __nv_bfloat16 hi = __float2bfloat16_rn(v);
    __nv_bfloat16 lo = __float2bfloat16_rn(v - __bfloat162float(hi));
    g_bh[idx] = hi;
    g_bl[idx] = lo;
}

// ===========================================================================
// GEMM: C = A @ W via ah*bh + ah*bl + al*bh, all operands bf16 via cp.async.
// CTA 128x128, 8 warps (2m x 4n), K chunks of 32, 80B smem row stride.
// Epilogue: per-(row,128col) int16 quantization.
// ===========================================================================
#define SM_AH0 0
#define SM_AH1 10240
#define SM_AL0 20480
#define SM_AL1 30720
#define SM_BH0 40960
#define SM_BH1 51200
#define SM_BL0 61440
#define SM_BL1 71680
#define SM_TOT 81920

__device__ __forceinline__ void cp16(uint32_t saddr, const void* g) {
    asm volatile("cp.async.cg.shared.global [%0], [%1], 16;" :: "r"(saddr), "l"(g));
}
__device__ __forceinline__ void cp_commit() { asm volatile("cp.async.commit_group;"); }
template <int N> __device__ __forceinline__ void cp_wait() {
    asm volatile("cp.async.wait_group %0;" :: "n"(N));
}
__device__ __forceinline__ void ldsm4(uint32_t& r0, uint32_t& r1, uint32_t& r2,
                                      uint32_t& r3, uint32_t addr) {
    asm volatile("ldmatrix.sync.aligned.m8n8.x4.shared.b16 {%0,%1,%2,%3}, [%4];"
                 : "=r"(r0), "=r"(r1), "=r"(r2), "=r"(r3) : "r"(addr));
}
__device__ __forceinline__ void mma16816(float* c, uint32_t a0, uint32_t a1,
                                         uint32_t a2, uint32_t a3,
                                         uint32_t b0, uint32_t b1) {
    asm volatile(
        "mma.sync.aligned.m16n8k16.row.col.f32.bf16.bf16.f32 "
        "{%0,%1,%2,%3}, {%4,%5,%6,%7}, {%8,%9}, {%0,%1,%2,%3};"
        : "+f"(c[0]), "+f"(c[1]), "+f"(c[2]), "+f"(c[3])
        : "r"(a0), "r"(a1), "r"(a2), "r"(a3), "r"(b0), "r"(b1));
}

__global__ __launch_bounds__(256) void k_gemm(
    const __nv_bfloat16* __restrict__ Ah,  // [8192 x 512]
    const __nv_bfloat16* __restrict__ Al,
    const __nv_bfloat16* __restrict__ Bh,  // [Ncol x 512] (layer slice)
    const __nv_bfloat16* __restrict__ Bl,
    unsigned short* __restrict__ Q,        // [8192 x Ncol]
    float* __restrict__ QS,                // [8192 x 4]
    int Ncol)
{
    extern __shared__ char sm[];
    const uint32_t sb = (uint32_t)__cvta_generic_to_shared(sm);

    int tid = threadIdx.x, wid = tid >> 5, lane = tid & 31;
    int g = lane >> 2, tig = lane & 3;
    int m0 = blockIdx.y * 128, n0 = blockIdx.x * 128;
    int wm = (wid >> 2) * 64, wn = (wid & 3) * 32;

    // cp.async mapping: 512 chunks of 16B per tile; thread covers chunks tid, tid+256
    int r0 = tid >> 2,        c0 = (tid & 3) * 8;     // 8 bf16 elements per chunk
    int r1 = (tid + 256) >> 2, c1 = (tid & 3) * 8;

    const __nv_bfloat16* Ahb = Ah + (size_t)m0 * 512;
    const __nv_bfloat16* Alb = Al + (size_t)m0 * 512;
    const __nv_bfloat16* Bhb = Bh + (size_t)n0 * 512;
    const __nv_bfloat16* Blb = Bl + (size_t)n0 * 512;

    const uint32_t AHo[2] = {sb + SM_AH0, sb + SM_AH1};
    const uint32_t ALo[2] = {sb + SM_AL0, sb + SM_AL1};
    const uint32_t BHo[2] = {sb + SM_BH0, sb + SM_BH1};
    const uint32_t BLo[2] = {sb + SM_BL0, sb + SM_BL1};

    uint32_t a_base = (uint32_t)((wm + (lane & 7) + ((lane >> 3) & 1) * 8) * 80
                                 + ((lane >> 4) & 1) * 16);
    uint32_t b_base = (uint32_t)((wn + (lane & 7) + ((lane >> 4) & 1) * 8) * 80
                                 + ((lane >> 3) & 1) * 16);

    float acc[4][4][4];
#pragma unroll
    for (int mt = 0; mt < 4; mt++)
#pragma unroll
        for (int nt = 0; nt < 4; nt++)
#pragma unroll
            for (int j = 0; j < 4; j++) acc[mt][nt][j] = 0.0f;

#define LOAD_CHUNK(buf, k0)                                                        \
    do {                                                                           \
        cp16(AHo[buf] + r0 * 80 + c0 * 2, Ahb + (size_t)r0 * 512 + (k0) + c0);     \
        cp16(AHo[buf] + r1 * 80 + c1 * 2, Ahb + (size_t)r1 * 512 + (k0) + c1);     \
        cp16(ALo[buf] + r0 * 80 + c0 * 2, Alb + (size_t)r0 * 512 + (k0) + c0);     \
        cp16(ALo[buf] + r1 * 80 + c1 * 2, Alb + (size_t)r1 * 512 + (k0) + c1);     \
        cp16(BHo[buf] + r0 * 80 + c0 * 2, Bhb + (size_t)r0 * 512 + (k0) + c0);     \
        cp16(BHo[buf] + r1 * 80 + c1 * 2, Bhb + (size_t)r1 * 512 + (k0) + c1);     \
        cp16(BLo[buf] + r0 * 80 + c0 * 2, Blb + (size_t)r0 * 512 + (k0) + c0);     \
        cp16(BLo[buf] + r1 * 80 + c1 * 2, Blb + (size_t)r1 * 512 + (k0) + c1);     \
        cp_commit();                                                               \
    } while (0)

    LOAD_CHUNK(0, 0);

    for (int k = 0; k < 16; k++) {
        int buf = k & 1;
        if (k < 15) {
            LOAD_CHUNK(buf ^ 1, (k + 1) * 32);
            cp_wait<1>();
        } else {
            cp_wait<0>();
        }
        __syncthreads();

#pragma unroll
        for (int ks2 = 0; ks2 < 2; ks2++) {
            uint32_t ksb = ks2 * 32;
            uint32_t bh[4][2], bl[4][2];
#pragma unroll
            for (int p = 0; p < 2; p++) {
                ldsm4(bh[2 * p][0], bh[2 * p][1], bh[2 * p + 1][0], bh[2 * p + 1][1],
                      BHo[buf] + b_base + p * 1280 + ksb);
                ldsm4(bl[2 * p][0], bl[2 * p][1], bl[2 * p + 1][0], bl[2 * p + 1][1],
                      BLo[buf] + b_base + p * 1280 + ksb);
            }
#pragma unroll
            for (int mt = 0; mt < 4; mt++) {
                uint32_t ah0, ah1, ah2, ah3, al0, al1, al2, al3;
                ldsm4(ah0, ah1, ah2, ah3, AHo[buf] + a_base + mt * 1280 + ksb);
                ldsm4(al0, al1, al2, al3, ALo[buf] + a_base + mt * 1280 + ksb);
#pragma unroll
                for (int nt = 0; nt < 4; nt++) {
                    mma16816(acc[mt][nt], ah0, ah1, ah2, ah3, bh[nt][0], bh[nt][1]);
                    mma16816(acc[mt][nt], ah0, ah1, ah2, ah3, bl[nt][0], bl[nt][1]);
                    mma16816(acc[mt][nt], al0, al1, al2, al3, bh[nt][0], bh[nt][1]);
                }
            }
        }
        __syncthreads();
    }

    // ---- epilogue: per-(row, CTA-col-block) scale -> int16 ----
    float* s_rm = (float*)sm;    // [128][4]

    float rmax[4][2];
#pragma unroll
    for (int mt = 0; mt < 4; mt++)
#pragma unroll
        for (int h = 0; h < 2; h++) {
            float m = 0.0f;
#pragma unroll
            for (int nt = 0; nt < 4; nt++)
                m = fmaxf(m, fmaxf(fabsf(acc[mt][nt][2 * h]), fabsf(acc[mt][nt][2 * h + 1])));
            m = fmaxf(m, __shfl_xor_sync(0xFFFFFFFFu, m, 1));
            m = fmaxf(m, __shfl_xor_sync(0xFFFFFFFFu, m, 2));
            rmax[mt][h] = m;
        }
    if (tig == 0) {
#pragma unroll
        for (int mt = 0; mt < 4; mt++)
#pragma unroll
            for (int h = 0; h < 2; h++)
                s_rm[(wm + mt * 16 + g + 8 * h) * 4 + (wid & 3)] = rmax[mt][h];
    }
    __syncthreads();

#pragma unroll
    for (int mt = 0; mt < 4; mt++)
#pragma unroll
        for (int h = 0; h < 2; h++) {
            int rl = wm + mt * 16 + g + 8 * h;
            float mx = fmaxf(fmaxf(s_rm[rl * 4 + 0], s_rm[rl * 4 + 1]),
                             fmaxf(s_rm[rl * 4 + 2], s_rm[rl * 4 + 3]));
            float inv = (mx > 0.0f) ? (32766.0f / mx) : 0.0f;
            if ((wid & 3) == 0 && tig == 0)
                QS[(size_t)(m0 + rl) * 4 + blockIdx.x] = mx * (1.0f / 32766.0f);
            size_t rowoff = (size_t)(m0 + rl) * Ncol + n0 + wn;
#pragma unroll
            for (int nt = 0; nt < 4; nt++) {
                uint32_t u0 = __float_as_uint(fmaf(acc[mt][nt][2 * h], inv, QMAGICF));
                uint32_t u1 = __float_as_uint(fmaf(acc[mt][nt][2 * h + 1], inv, QMAGICF));
                *(uint32_t*)&Q[rowoff + nt * 8 + tig * 2] = __byte_perm(u0, u1, 0x5410);
            }
        }
}

// ===========================================================================
// SpMM: int16 gather + exact dequant.
// MODE 0: fp32 output (final layer, no relu)
// MODE 1: relu + bf16 (hi,lo) split output for next GEMM
// ===========================================================================
__device__ __forceinline__ void deq_fma(float4& a, float w, uint2 u) {
    uint32_t p0 = __byte_perm(u.x, 0x4B000000u, 0x7410);
    uint32_t p1 = __byte_perm(u.x, 0x4B000000u, 0x7432);
    uint32_t p2 = __byte_perm(u.y, 0x4B000000u, 0x7410);
    uint32_t p3 = __byte_perm(u.y, 0x4B000000u, 0x7432);
    a.x += w * (__uint_as_float(p0) - QMAGICF);
    a.y += w * (__uint_as_float(p1) - QMAGICF);
    a.z += w * (__uint_as_float(p2) - QMAGICF);
    a.w += w * (__uint_as_float(p3) - QMAGICF);
}

template <int NCOL, int NB, int MODE>
__global__ __launch_bounds__(NCOL / 4) void k_spmm(const unsigned short* __restrict__ q,
                                                   const float* __restrict__ qs,
                                                   const float* __restrict__ bias,
                                                   float* __restrict__ outf,
                                                   __nv_bfloat16* __restrict__ oah,
                                                   __nv_bfloat16* __restrict__ oal) {
    constexpr int T = NCOL / 4;
    int row = blockIdx.x;
    int tid = threadIdx.x;

    __shared__ int   s_cols[MAXDEG];
    __shared__ float s_w[MAXDEG * NB];

    int n = g_cnt[row];
    for (int t = tid; t < n; t += T) {
        int j = g_cols[(size_t)row * MAXDEG + t];
        s_cols[t] = j;
        float dj = g_dinv[j];
#pragma unroll
        for (int b = 0; b < NB; b++) s_w[t * NB + b] = dj * qs[(size_t)j * 4 + b];
    }
    __syncthreads();

    int nb = tid >> 5;
    const uint2* qp = (const uint2*)q;

    float4 acc = make_float4(0.0f, 0.0f, 0.0f, 0.0f);
    {
        float ws = g_selfcoef[row] * qs[(size_t)row * 4 + nb];
        deq_fma(acc, ws, qp[(size_t)row * T + tid]);
    }

    int t = 0;
    for (; t + 8 <= n; t += 8) {
        uint2 u[8];
        float w[8];
#pragma unroll
        for (int i = 0; i < 8; i++) {
            int j = s_cols[t + i];
            w[i] = s_w[(t + i) * NB + nb];
            u[i] = qp[(size_t)j * T + tid];
        }
#pragma unroll
        for (int i = 0; i < 8; i++) deq_fma(acc, w[i], u[i]);
    }
    for (; t < n; t++) {
        uint2 u = qp[(size_t)s_cols[t] * T + tid];
        deq_fma(acc, s_w[t * NB + nb], u);
    }

    float di = g_dinv[row];
    float4 bv = ((const float4*)bias)[tid];
    float4 r;
    r.x = di * acc.x + bv.x;
    r.y = di * acc.y + bv.y;
    r.z = di * acc.z + bv.z;
    r.w = di * acc.w + bv.w;

    if (MODE == 0) {
        ((float4*)outf)[(size_t)row * T + tid] = r;
    } else {
        r.x = fmaxf(r.x, 0.0f); r.y = fmaxf(r.y, 0.0f);
        r.z = fmaxf(r.z, 0.0f); r.w = fmaxf(r.w, 0.0f);
        float hx = __bfloat162float(__float2bfloat16_rn(r.x));
        float hy = __bfloat162float(__float2bfloat16_rn(r.y));
        float hz = __bfloat162float(__float2bfloat16_rn(r.z));
        float hw = __bfloat162float(__float2bfloat16_rn(r.w));
        ((uint2*)oah)[(size_t)row * T + tid] =
            make_uint2(packbf2(r.x, r.y), packbf2(r.z, r.w));
        ((uint2*)oal)[(size_t)row * T + tid] =
            make_uint2(packbf2(r.x - hx, r.y - hy), packbf2(r.z - hz, r.w - hw));
    }
}

// ===========================================================================
extern "C" void kernel_launch(void* const* d_in, const int* in_sizes, int n_in,
                              void* d_out, int out_size) {
    const float* x  = (const float*)d_in[0];
    const int*   ei = (const int*)d_in[1];
    const float* W1 = (const float*)d_in[2];
    const float* b1 = (const float*)d_in[3];
    const float* W2 = (const float*)d_in[4];
    const float* b2 = (const float*)d_in[5];
    const float* W3 = (const float*)d_in[6];
    const float* b3 = (const float*)d_in[7];
    float* out = (float*)d_out;

    int E = in_sizes[1] / 2;

    void *pah, *pal, *pbh, *pbl, *pq, *pqs;
    cudaGetSymbolAddress(&pah, g_ah);
    cudaGetSymbolAddress(&pal, g_al);
    cudaGetSymbolAddress(&pbh, g_bh);
    cudaGetSymbolAddress(&pbl, g_bl);
    cudaGetSymbolAddress(&pq, g_q);
    cudaGetSymbolAddress(&pqs, g_qs);
    __nv_bfloat16* ah = (__nv_bfloat16*)pah;
    __nv_bfloat16* al = (__nv_bfloat16*)pal;
    __nv_bfloat16* bh = (__nv_bfloat16*)pbh;
    __nv_bfloat16* bl = (__nv_bfloat16*)pbl;
    unsigned short* qb = (unsigned short*)pq;
    float* qsb = (float*)pqs;

    cudaFuncSetAttribute(k_gemm, cudaFuncAttributeMaxDynamicSharedMemorySize, SM_TOT);

    // --- graph build + input/weight expansion ---
    k_clear_detect<<<NNODES * WORDS_PER_ROW / 256, 256>>>(ei, E);
    k_scatter<<<(E + 255) / 256, 256>>>(ei, E);
    k_build_rows<<<NNODES / 8, 256>>>();
    k_expandX<<<NNODES * FDIM / 4 / 256, 256>>>(x, ah, al);
    k_expandB_all<<<(655360 + 255) / 256, 256>>>(W1, W2, W3);

    dim3 g512(4, 64);
    dim3 g256(2, 64);

    // layer 1
    k_gemm<<<g512, 256, SM_TOT>>>(ah, al, bh, bl, qb, qsb, 512);
    k_spmm<512, 4, 1><<<NNODES, 128>>>(qb, qsb, b1, nullptr, ah, al);

    // layer 2
    k_gemm<<<g512, 256, SM_TOT>>>(ah, al, bh + 262144, bl + 262144, qb, qsb, 512);
    k_spmm<512, 4, 1><<<NNODES, 128>>>(qb, qsb, b2, nullptr, ah, al);

    // layer 3
    k_gemm<<<g256, 256, SM_TOT>>>(ah, al, bh + 524288, bl + 524288, qb, qsb, 256);
    k_spmm<256, 2, 0><<<NNODES, 64>>>(qb, qsb, b3, out, nullptr, nullptr);
}

// round 8
// speedup vs baseline: 1.3598x; 1.0418x over previous
#include <cuda_runtime.h>
#include <cuda_bf16.h>
#include <cstdint>

// ===========================================================================
// GCN: out = Anorm @ relu(Anorm @ relu(Anorm @ (x W1) + b1) W2 + b2) W3 + b3
// Activations carried as bf16 (hi,lo) split pairs. GEMM: bf16 mma.sync,
// 3-term split, all-cp.async pipeline, 2 CTAs/SM, int16-quantizing epilogue.
// SpMM: int16 gather, exact PRMT/FADD dequant.
// ===========================================================================

#define NNODES 8192
#define FDIM   512
#define WORDS_PER_ROW 256
#define MAXDEG 192
#define QMAGICF 8421376.0f    // 2^23 + 32768

__device__ unsigned int g_bits[NNODES * WORDS_PER_ROW];   // 8 MB
__device__ unsigned int g_self[WORDS_PER_ROW];
__device__ float g_dinv[NNODES];
__device__ float g_selfcoef[NNODES];
__device__ int   g_cols[NNODES * MAXDEG];
__device__ int   g_cnt[NNODES];
__device__ int   g_is64;
__device__ __nv_bfloat16 g_ah[NNODES * FDIM];             // 8 MB activation hi
__device__ __nv_bfloat16 g_al[NNODES * FDIM];             // 8 MB activation lo
// W splits for all 3 layers: [0]=W1(512x512), [262144]=W2, [524288]=W3(256x512)
__device__ __nv_bfloat16 g_bh[655360];
__device__ __nv_bfloat16 g_bl[655360];
__device__ unsigned short g_q[NNODES * FDIM];             // quantized GEMM out
__device__ float g_qs[NNODES * 4];                        // per-(row,128col) scale

// ===========================================================================
// Graph build
// ===========================================================================
__global__ void k_clear_detect(const int* __restrict__ ei, int E) {
    int idx = blockIdx.x * blockDim.x + threadIdx.x;
    int row = idx >> 8;
    int w   = idx & 255;
    g_bits[idx] = (w == (row >> 5)) ? (1u << (row & 31)) : 0u;
    if (idx < WORDS_PER_ROW) g_self[idx] = 0u;
    if (idx == 0) g_is64 = 1;
    if (idx < E) {
        if (ei[2 * idx + 1] != 0) g_is64 = 0;
    }
}

__global__ void k_scatter(const int* __restrict__ w, int E) {
    int i = blockIdx.x * blockDim.x + threadIdx.x;
    if (i >= E) return;
    int a, b;
    if (g_is64) { a = w[2 * i]; b = w[2 * E + 2 * i]; }
    else        { a = w[i];     b = w[E + i]; }
    if ((unsigned)a >= NNODES || (unsigned)b >= NNODES) return;
    atomicOr(&g_bits[(size_t)a * WORDS_PER_ROW + (b >> 5)], 1u << (b & 31));
    atomicOr(&g_bits[(size_t)b * WORDS_PER_ROW + (a >> 5)], 1u << (a & 31));
    if (a == b) atomicOr(&g_self[a >> 5], 1u << (a & 31));
}

__global__ void k_build_rows() {
    int warp = (blockIdx.x * blockDim.x + threadIdx.x) >> 5;
    int lane = threadIdx.x & 31;
    if (warp >= NNODES) return;
    int row = warp;

    unsigned int w[8];
    const unsigned int* base = &g_bits[(size_t)row * WORDS_PER_ROW + lane * 8];
#pragma unroll
    for (int t = 0; t < 8; t++) w[t] = base[t];

    int dw = row >> 5;
    if ((dw >> 3) == lane) w[dw & 7] &= ~(1u << (row & 31));

    unsigned int cnt = 0;
#pragma unroll
    for (int t = 0; t < 8; t++) cnt += __popc(w[t]);

    unsigned int incl = cnt;
#pragma unroll
    for (int d = 1; d < 32; d <<= 1) {
        unsigned int v = __shfl_up_sync(0xFFFFFFFFu, incl, d);
        if (lane >= d) incl += v;
    }
    unsigned int excl  = incl - cnt;
    unsigned int total = __shfl_sync(0xFFFFFFFFu, incl, 31);

    int* cols = &g_cols[(size_t)row * MAXDEG];
    unsigned int o = excl;
#pragma unroll
    for (int t = 0; t < 8; t++) {
        unsigned int bits = w[t];
        int colbase = (lane * 8 + t) * 32;
        while (bits) {
            int b = __ffs(bits) - 1;
            bits &= bits - 1;
            if (o < MAXDEG) cols[o] = colbase + b;
            o++;
        }
    }

    if (lane == 0) {
        int self = (g_self[row >> 5] >> (row & 31)) & 1;
        float deg = (float)total + 1.0f + (float)self;
        float di = rsqrtf(deg);
        g_dinv[row] = di;
        g_selfcoef[row] = (1.0f + (float)self) * di;
        g_cnt[row] = (int)(total < MAXDEG ? total : MAXDEG);
    }
}

// ===========================================================================
// expand_all: block range [0, 4096)   -> x fp32 -> (ah, al) split (float4 lanes)
//             block range [4096, 6656)-> W1/W2/W3 -> n-major bf16 hi/lo
// ===========================================================================
__device__ __forceinline__ uint32_t packbf2(float x, float y) {
    __nv_bfloat162 t = __floats2bfloat162_rn(x, y);
    return *(uint32_t*)&t;
}

__global__ void k_expand_all(const float* __restrict__ X,
                             const float* __restrict__ W1,
                             const float* __restrict__ W2,
                             const float* __restrict__ W3) {
    int bid = blockIdx.x;
    if (bid < 4096) {
        int idx = bid * 256 + threadIdx.x;           // over (8192*512)/4
        float4 v = ((const float4*)X)[idx];
        float hx = __bfloat162float(__float2bfloat16_rn(v.x));
        float hy = __bfloat162float(__float2bfloat16_rn(v.y));
        float hz = __bfloat162float(__float2bfloat16_rn(v.z));
        float hw = __bfloat162float(__float2bfloat16_rn(v.w));
        ((uint2*)g_ah)[idx] = make_uint2(packbf2(v.x, v.y), packbf2(v.z, v.w));
        ((uint2*)g_al)[idx] = make_uint2(packbf2(v.x - hx, v.y - hy),
                                         packbf2(v.z - hz, v.w - hw));
    } else {
        int idx = (bid - 4096) * 256 + threadIdx.x;  // over 655360
        if (idx >= 655360) return;
        const float* W;
        int Ncol, local;
        if (idx < 262144)      { W = W1; Ncol = 512; local = idx; }
        else if (idx < 524288) { W = W2; Ncol = 512; local = idx - 262144; }
        else                   { W = W3; Ncol = 256; local = idx - 524288; }
        int n = local >> 9;
        int k = local & 511;
        float v = W[(size_t)k * Ncol + n];
        __nv_bfloat16 hi = __float2bfloat16_rn(v);
        __nv_bfloat16 lo = __float2bfloat16_rn(v - __bfloat162float(hi));
        g_bh[idx] = hi;
        g_bl[idx] = lo;
    }
}

// ===========================================================================
// GEMM: C = A @ W via ah*bh + ah*bl + al*bh. 2 CTAs/SM, single-sync pipeline.
// CTA 128x128, 8 warps (2m x 4n), K chunks of 32, 80B smem row stride.
// ===========================================================================
#define SM_AH0 0
#define SM_AH1 10240
#define SM_AL0 20480
#define SM_AL1 30720
#define SM_BH0 40960
#define SM_BH1 51200
#define SM_BL0 61440
#define SM_BL1 71680
#define SM_TOT 81920

__device__ __forceinline__ void cp16(uint32_t saddr, const void* g) {
    asm volatile("cp.async.cg.shared.global [%0], [%1], 16;" :: "r"(saddr), "l"(g));
}
__device__ __forceinline__ void cp_commit() { asm volatile("cp.async.commit_group;"); }
template <int N> __device__ __forceinline__ void cp_wait() {
    asm volatile("cp.async.wait_group %0;" :: "n"(N));
}
__device__ __forceinline__ void ldsm4(uint32_t& r0, uint32_t& r1, uint32_t& r2,
                                      uint32_t& r3, uint32_t addr) {
    asm volatile("ldmatrix.sync.aligned.m8n8.x4.shared.b16 {%0,%1,%2,%3}, [%4];"
                 : "=r"(r0), "=r"(r1), "=r"(r2), "=r"(r3) : "r"(addr));
}
__device__ __forceinline__ void mma16816(float* c, uint32_t a0, uint32_t a1,
                                         uint32_t a2, uint32_t a3,
                                         uint32_t b0, uint32_t b1) {
    asm volatile(
        "mma.sync.aligned.m16n8k16.row.col.f32.bf16.bf16.f32 "
        "{%0,%1,%2,%3}, {%4,%5,%6,%7}, {%8,%9}, {%0,%1,%2,%3};"
        : "+f"(c[0]), "+f"(c[1]), "+f"(c[2]), "+f"(c[3])
        : "r"(a0), "r"(a1), "r"(a2), "r"(a3), "r"(b0), "r"(b1));
}

__global__ __launch_bounds__(256, 2) void k_gemm(
    const __nv_bfloat16* __restrict__ Ah,
    const __nv_bfloat16* __restrict__ Al,
    const __nv_bfloat16* __restrict__ Bh,
    const __nv_bfloat16* __restrict__ Bl,
    unsigned short* __restrict__ Q,
    float* __restrict__ QS,
    int Ncol)
{
    extern __shared__ char sm[];
    const uint32_t sb = (uint32_t)__cvta_generic_to_shared(sm);

    int tid = threadIdx.x, wid = tid >> 5, lane = tid & 31;
    int g = lane >> 2, tig = lane & 3;
    int m0 = blockIdx.y * 128, n0 = blockIdx.x * 128;
    int wm = (wid >> 2) * 64, wn = (wid & 3) * 32;

    int r0 = tid >> 2,         c0 = (tid & 3) * 8;
    int r1 = (tid + 256) >> 2, c1 = (tid & 3) * 8;

    const __nv_bfloat16* Ahb = Ah + (size_t)m0 * 512;
    const __nv_bfloat16* Alb = Al + (size_t)m0 * 512;
    const __nv_bfloat16* Bhb = Bh + (size_t)n0 * 512;
    const __nv_bfloat16* Blb = Bl + (size_t)n0 * 512;

    const uint32_t AHo[2] = {sb + SM_AH0, sb + SM_AH1};
    const uint32_t ALo[2] = {sb + SM_AL0, sb + SM_AL1};
    const uint32_t BHo[2] = {sb + SM_BH0, sb + SM_BH1};
    const uint32_t BLo[2] = {sb + SM_BL0, sb + SM_BL1};

    uint32_t a_base = (uint32_t)((wm + (lane & 7) + ((lane >> 3) & 1) * 8) * 80
                                 + ((lane >> 4) & 1) * 16);
    uint32_t b_base = (uint32_t)((wn + (lane & 7) + ((lane >> 4) & 1) * 8) * 80
                                 + ((lane >> 3) & 1) * 16);

    float acc[4][4][4];
#pragma unroll
    for (int mt = 0; mt < 4; mt++)
#pragma unroll
        for (int nt = 0; nt < 4; nt++)
#pragma unroll
            for (int j = 0; j < 4; j++) acc[mt][nt][j] = 0.0f;

#define LOAD_CHUNK(buf, k0)                                                        \
    do {                                                                           \
        cp16(AHo[buf] + r0 * 80 + c0 * 2, Ahb + (size_t)r0 * 512 + (k0) + c0);     \
        cp16(AHo[buf] + r1 * 80 + c1 * 2, Ahb + (size_t)r1 * 512 + (k0) + c1);     \
        cp16(ALo[buf] + r0 * 80 + c0 * 2, Alb + (size_t)r0 * 512 + (k0) + c0);     \
        cp16(ALo[buf] + r1 * 80 + c1 * 2, Alb + (size_t)r1 * 512 + (k0) + c1);     \
        cp16(BHo[buf] + r0 * 80 + c0 * 2, Bhb + (size_t)r0 * 512 + (k0) + c0);     \
        cp16(BHo[buf] + r1 * 80 + c1 * 2, Bhb + (size_t)r1 * 512 + (k0) + c1);     \
        cp16(BLo[buf] + r0 * 80 + c0 * 2, Blb + (size_t)r0 * 512 + (k0) + c0);     \
        cp16(BLo[buf] + r1 * 80 + c1 * 2, Blb + (size_t)r1 * 512 + (k0) + c1);     \
        cp_commit();                                                               \
    } while (0)

    LOAD_CHUNK(0, 0);

    for (int k = 0; k < 16; k++) {
        int buf = k & 1;
        cp_wait<0>();          // buf k's data has arrived
        __syncthreads();       // visible to all; all warps done reading buf k-1
        if (k < 15) LOAD_CHUNK(buf ^ 1, (k + 1) * 32);   // overwrites buf k-1: safe

#pragma unroll
        for (int ks2 = 0; ks2 < 2; ks2++) {
            uint32_t ksb = ks2 * 32;
            uint32_t bh[4][2], bl[4][2];
#pragma unroll
            for (int p = 0; p < 2; p++) {
                ldsm4(bh[2 * p][0], bh[2 * p][1], bh[2 * p + 1][0], bh[2 * p + 1][1],
                      BHo[buf] + b_base + p * 1280 + ksb);
                ldsm4(bl[2 * p][0], bl[2 * p][1], bl[2 * p + 1][0], bl[2 * p + 1][1],
                      BLo[buf] + b_base + p * 1280 + ksb);
            }
#pragma unroll
            for (int mt = 0; mt < 4; mt++) {
                uint32_t ah0, ah1, ah2, ah3, al0, al1, al2, al3;
                ldsm4(ah0, ah1, ah2, ah3, AHo[buf] + a_base + mt * 1280 + ksb);
                ldsm4(al0, al1, al2, al3, ALo[buf] + a_base + mt * 1280 + ksb);
#pragma unroll
                for (int nt = 0; nt < 4; nt++) {
                    mma16816(acc[mt][nt], ah0, ah1, ah2, ah3, bh[nt][0], bh[nt][1]);
                    mma16816(acc[mt][nt], ah0, ah1, ah2, ah3, bl[nt][0], bl[nt][1]);
                    mma16816(acc[mt][nt], al0, al1, al2, al3, bh[nt][0], bh[nt][1]);
                }
            }
        }
        __syncthreads();       // all warps done reading buf k before next overwrite wait
    }

    // ---- epilogue: per-(row, CTA-col-block) scale -> int16 ----
    float* s_rm = (float*)sm;    // [128][4]

    float rmax[4][2];
#pragma unroll
    for (int mt = 0; mt < 4; mt++)
#pragma unroll
        for (int h = 0; h < 2; h++) {
            float m = 0.0f;
#pragma unroll
            for (int nt = 0; nt < 4; nt++)
                m = fmaxf(m, fmaxf(fabsf(acc[mt][nt][2 * h]), fabsf(acc[mt][nt][2 * h + 1])));
            m = fmaxf(m, __shfl_xor_sync(0xFFFFFFFFu, m, 1));
            m = fmaxf(m, __shfl_xor_sync(0xFFFFFFFFu, m, 2));
            rmax[mt][h] = m;
        }
    if (tig == 0) {
#pragma unroll
        for (int mt = 0; mt < 4; mt++)
#pragma unroll
            for (int h = 0; h < 2; h++)
                s_rm[(wm + mt * 16 + g + 8 * h) * 4 + (wid & 3)] = rmax[mt][h];
    }
    __syncthreads();

#pragma unroll
    for (int mt = 0; mt < 4; mt++)
#pragma unroll
        for (int h = 0; h < 2; h++) {
            int rl = wm + mt * 16 + g + 8 * h;
            float mx = fmaxf(fmaxf(s_rm[rl * 4 + 0], s_rm[rl * 4 + 1]),
                             fmaxf(s_rm[rl * 4 + 2], s_rm[rl * 4 + 3]));
            float inv = (mx > 0.0f) ? (32766.0f / mx) : 0.0f;
            if ((wid & 3) == 0 && tig == 0)
                QS[(size_t)(m0 + rl) * 4 + blockIdx.x] = mx * (1.0f / 32766.0f);
            size_t rowoff = (size_t)(m0 + rl) * Ncol + n0 + wn;
#pragma unroll
            for (int nt = 0; nt < 4; nt++) {
                uint32_t u0 = __float_as_uint(fmaf(acc[mt][nt][2 * h], inv, QMAGICF));
                uint32_t u1 = __float_as_uint(fmaf(acc[mt][nt][2 * h + 1], inv, QMAGICF));
                *(uint32_t*)&Q[rowoff + nt * 8 + tig * 2] = __byte_perm(u0, u1, 0x5410);
            }
        }
}

// ===========================================================================
// SpMM: int16 gather + exact dequant.
// MODE 0: fp32 output (final layer, no relu)
// MODE 1: relu + bf16 (hi,lo) split output for next GEMM
// ===========================================================================
__device__ __forceinline__ void deq_fma(float4& a, float w, uint2 u) {
    uint32_t p0 = __byte_perm(u.x, 0x4B000000u, 0x7410);
    uint32_t p1 = __byte_perm(u.x, 0x4B000000u, 0x7432);
    uint32_t p2 = __byte_perm(u.y, 0x4B000000u, 0x7410);
    uint32_t p3 = __byte_perm(u.y, 0x4B000000u, 0x7432);
    a.x += w * (__uint_as_float(p0) - QMAGICF);
    a.y += w * (__uint_as_float(p1) - QMAGICF);
    a.z += w * (__uint_as_float(p2) - QMAGICF);
    a.w += w * (__uint_as_float(p3) - QMAGICF);
}

template <int NCOL, int NB, int MODE>
__global__ __launch_bounds__(NCOL / 4) void k_spmm(const unsigned short* __restrict__ q,
                                                   const float* __restrict__ qs,
                                                   const float* __restrict__ bias,
                                                   float* __restrict__ outf,
                                                   __nv_bfloat16* __restrict__ oah,
                                                   __nv_bfloat16* __restrict__ oal) {
    constexpr int T = NCOL / 4;
    int row = blockIdx.x;
    int tid = threadIdx.x;

    __shared__ int   s_cols[MAXDEG];
    __shared__ float s_w[MAXDEG * NB];

    int n = g_cnt[row];
    for (int t = tid; t < n; t += T) {
        int j = g_cols[(size_t)row * MAXDEG + t];
        s_cols[t] = j;
        float dj = g_dinv[j];
#pragma unroll
        for (int b = 0; b < NB; b++) s_w[t * NB + b] = dj * qs[(size_t)j * 4 + b];
    }
    __syncthreads();

    int nb = tid >> 5;
    const uint2* qp = (const uint2*)q;

    float4 acc = make_float4(0.0f, 0.0f, 0.0f, 0.0f);
    {
        float ws = g_selfcoef[row] * qs[(size_t)row * 4 + nb];
        deq_fma(acc, ws, qp[(size_t)row * T + tid]);
    }

    int t = 0;
    for (; t + 8 <= n; t += 8) {
        uint2 u[8];
        float w[8];
#pragma unroll
        for (int i = 0; i < 8; i++) {
            int j = s_cols[t + i];
            w[i] = s_w[(t + i) * NB + nb];
            u[i] = qp[(size_t)j * T + tid];
        }
#pragma unroll
        for (int i = 0; i < 8; i++) deq_fma(acc, w[i], u[i]);
    }
    for (; t < n; t++) {
        uint2 u = qp[(size_t)s_cols[t] * T + tid];
        deq_fma(acc, s_w[t * NB + nb], u);
    }

    float di = g_dinv[row];
    float4 bv = ((const float4*)bias)[tid];
    float4 r;
    r.x = di * acc.x + bv.x;
    r.y = di * acc.y + bv.y;
    r.z = di * acc.z + bv.z;
    r.w = di * acc.w + bv.w;

    if (MODE == 0) {
        ((float4*)outf)[(size_t)row * T + tid] = r;
    } else {
        r.x = fmaxf(r.x, 0.0f); r.y = fmaxf(r.y, 0.0f);
        r.z = fmaxf(r.z, 0.0f); r.w = fmaxf(r.w, 0.0f);
        float hx = __bfloat162float(__float2bfloat16_rn(r.x));
        float hy = __bfloat162float(__float2bfloat16_rn(r.y));
        float hz = __bfloat162float(__float2bfloat16_rn(r.z));
        float hw = __bfloat162float(__float2bfloat16_rn(r.w));
        ((uint2*)oah)[(size_t)row * T + tid] =
            make_uint2(packbf2(r.x, r.y), packbf2(r.z, r.w));
        ((uint2*)oal)[(size_t)row * T + tid] =
            make_uint2(packbf2(r.x - hx, r.y - hy), packbf2(r.z - hz, r.w - hw));
    }
}

// ===========================================================================
extern "C" void kernel_launch(void* const* d_in, const int* in_sizes, int n_in,
                              void* d_out, int out_size) {
    const float* x  = (const float*)d_in[0];
    const int*   ei = (const int*)d_in[1];
    const float* W1 = (const float*)d_in[2];
    const float* b1 = (const float*)d_in[3];
    const float* W2 = (const float*)d_in[4];
    const float* b2 = (const float*)d_in[5];
    const float* W3 = (const float*)d_in[6];
    const float* b3 = (const float*)d_in[7];
    float* out = (float*)d_out;

    int E = in_sizes[1] / 2;

    void *pah, *pal, *pbh, *pbl, *pq, *pqs;
    cudaGetSymbolAddress(&pah, g_ah);
    cudaGetSymbolAddress(&pal, g_al);
    cudaGetSymbolAddress(&pbh, g_bh);
    cudaGetSymbolAddress(&pbl, g_bl);
    cudaGetSymbolAddress(&pq, g_q);
    cudaGetSymbolAddress(&pqs, g_qs);
    __nv_bfloat16* ah = (__nv_bfloat16*)pah;
    __nv_bfloat16* al = (__nv_bfloat16*)pal;
    __nv_bfloat16* bh = (__nv_bfloat16*)pbh;
    __nv_bfloat16* bl = (__nv_bfloat16*)pbl;
    unsigned short* qb = (unsigned short*)pq;
    float* qsb = (float*)pqs;

    cudaFuncSetAttribute(k_gemm, cudaFuncAttributeMaxDynamicSharedMemorySize, SM_TOT);

    // --- graph build + expansions ---
    k_clear_detect<<<NNODES * WORDS_PER_ROW / 256, 256>>>(ei, E);
    k_scatter<<<(E + 255) / 256, 256>>>(ei, E);
    k_build_rows<<<NNODES / 8, 256>>>();
    k_expand_all<<<4096 + 2560, 256>>>(x, W1, W2, W3);

    dim3 g512(4, 64);
    dim3 g256(2, 64);

    // layer 1
    k_gemm<<<g512, 256, SM_TOT>>>(ah, al, bh, bl, qb, qsb, 512);
    k_spmm<512, 4, 1><<<NNODES, 128>>>(qb, qsb, b1, nullptr, ah, al);

    // layer 2
    k_gemm<<<g512, 256, SM_TOT>>>(ah, al, bh + 262144, bl + 262144, qb, qsb, 512);
    k_spmm<512, 4, 1><<<NNODES, 128>>>(qb, qsb, b2, nullptr, ah, al);

    // layer 3
    k_gemm<<<g256, 256, SM_TOT>>>(ah, al, bh + 524288, bl + 524288, qb, qsb, 256);
    k_spmm<256, 2, 0><<<NNODES, 64>>>(qb, qsb, b3, out, nullptr, nullptr);
}